// round 15
// baseline (speedup 1.0000x reference)
#include <cuda_runtime.h>
#include <cuda_fp16.h>

#define NN 100000
#define EE 1600000
#define TN (3 * NN)
#define DD 128
#define D2 64             // half2 per row
#define RR 400
#define LN_EPS 1e-5f
#define ASTR2 137         // As smem stride in half2 words
#define BSTR2 136         // Bs smem stride in half2 words (mult of 4; conflict-free mma loads)
#define SCAN_BLK 4096
#define NBLK ((TN + SCAN_BLK - 1) / SCAN_BLK)   // 74  (< 148 SMs => whole grid resident)

// prep kernel block ranges (pack weights + convert x + per-bucket degree count, 4 edges/thread)
#define PREP_PACK_BLKS 256        // 8 * 8192 half2 / 256
#define PREP_XCV_BLKS 12500       // NN*D2/2 uint2 / 256
#define PREP_CNT_BLKS 1563        // ceil(EE/4/256)
#define PREP_BLKS (PREP_PACK_BLKS + PREP_XCV_BLKS + PREP_CNT_BLKS)

// ---- scratch (static device globals; no allocations allowed) ----
__device__ __align__(16) unsigned g_aggu[(size_t)TN * D2];  // aggregated features, half2
__device__ __align__(16) unsigned g_xu[(size_t)NN * D2];    // node_emb as half2 (transform phase-2)
__device__ __align__(16) unsigned g_x1u[(size_t)NN * D2];   // layer-1 output as half2 (transform phase-2)
__device__ __align__(16) float    g_x1f[(size_t)NN * DD];   // layer-1 output as fp32 (gather input)
__device__ int      g_cnt[TN];                  // statically zero; re-zeroed in transform(1) tail
__device__ int      g_rowptr[TN];
__device__ int      g_cur[TN];
__device__ int      g_blk[128];
__device__ int      g_bar;                      // scan grid barrier; reset by fill_kernel
__device__ int      g_eidx[EE];
__device__ unsigned g_Wtu[2][3 * D2 * DD];      // relation weights, k-pair-major half2: [d2][o]
__device__ unsigned g_Wstu[2][D2 * DD];         // self weights, same layout

__device__ __forceinline__ unsigned pack_h2(float a, float b) {
    __half2 h = __floats2half2_rn(a, b);
    return *reinterpret_cast<unsigned*>(&h);
}
__device__ __forceinline__ float2 unpack_h2(unsigned u) {
    return __half22float2(*reinterpret_cast<__half2*>(&u));
}

__device__ __forceinline__ void mma_f16(float* c, const unsigned* a, unsigned b0, unsigned b1) {
    asm volatile(
        "mma.sync.aligned.m16n8k16.row.col.f32.f16.f16.f32 "
        "{%0,%1,%2,%3},{%4,%5,%6,%7},{%8,%9},{%0,%1,%2,%3};\n"
        : "+f"(c[0]), "+f"(c[1]), "+f"(c[2]), "+f"(c[3])
        : "r"(a[0]), "r"(a[1]), "r"(a[2]), "r"(a[3]), "r"(b0), "r"(b1));
}

// ---- fused prep: pack weights; convert x to half2; degree count (4 edges/thread) ----
__global__ void prep_kernel(const float* __restrict__ W1, const float* __restrict__ Ws1,
                            const float* __restrict__ W2, const float* __restrict__ Ws2,
                            const float* __restrict__ x, const int* __restrict__ edges) {
    int b = blockIdx.x;
    int tid = threadIdx.x;
    if (b < PREP_PACK_BLKS) {
        int idx = b * 256 + tid;                 // 8 matrices * 8192 half2
        int m = idx >> 13;
        int e = idx & (D2 * DD - 1);
        int d2 = e >> 7;                         // k-pair index 0..63
        int o = e & 127;
        const float* src;
        unsigned* dst;
        if (m < 3)       { src = W1 + m * DD * DD;       dst = g_Wtu[0] + m * D2 * DD; }
        else if (m == 3) { src = Ws1;                    dst = g_Wstu[0]; }
        else if (m < 7)  { src = W2 + (m - 4) * DD * DD; dst = g_Wtu[1] + (m - 4) * D2 * DD; }
        else             { src = Ws2;                    dst = g_Wstu[1]; }
        dst[d2 * DD + o] = pack_h2(src[o * DD + 2 * d2], src[o * DD + 2 * d2 + 1]);
    } else if (b < PREP_PACK_BLKS + PREP_XCV_BLKS) {
        int i = (b - PREP_PACK_BLKS) * 256 + tid;   // NN*D2/2 uint2 stores
        float4 v = __ldg((const float4*)x + i);
        uint2 o;
        o.x = pack_h2(v.x, v.y);
        o.y = pack_h2(v.z, v.w);
        ((uint2*)g_xu)[i] = o;
    } else {
        // degree count: 4 edges per thread via 3 aligned uint4 loads (MLP=4 atomics)
        int e4 = (b - PREP_PACK_BLKS - PREP_XCV_BLKS) * 256 + tid;
        if (e4 < EE / 4) {
            const uint4* ep = (const uint4*)(edges + 12 * e4);
            uint4 v0 = __ldcs(ep + 0);   // s0 r0 d0 s1
            uint4 v1 = __ldcs(ep + 1);   // r1 d1 s2 r2
            uint4 v2 = __ldcs(ep + 2);   // d2 s3 r3 d3
            int r0 = (int)v0.y, d0 = (int)v0.z;
            int r1 = (int)v1.x, d1 = (int)v1.y;
            int r2 = (int)v1.w, d2 = (int)v2.x;
            int r3 = (int)v2.z, d3 = (int)v2.w;
            atomicAdd(&g_cnt[((r0 >= RR) + (r0 >= 2 * RR)) * NN + d0], 1);
            atomicAdd(&g_cnt[((r1 >= RR) + (r1 >= 2 * RR)) * NN + d1], 1);
            atomicAdd(&g_cnt[((r2 >= RR) + (r2 >= 2 * RR)) * NN + d2], 1);
            atomicAdd(&g_cnt[((r3 >= RR) + (r3 >= 2 * RR)) * NN + d3], 1);
        }
    }
}

// ---- fused exclusive scan (single kernel, resident-grid spin barrier) ----
__global__ __launch_bounds__(256) void scan_fused_kernel() {
    __shared__ int sm[256];
    const int tid = threadIdx.x;
    const int bid = blockIdx.x;
    const int base = bid * SCAN_BLK + tid * 16;
    int c[16];
    int run = 0;
#pragma unroll
    for (int t = 0; t < 16; t++) {
        int v = (base + t < TN) ? g_cnt[base + t] : 0;
        c[t] = run;
        run += v;
    }
    sm[tid] = run;
    __syncthreads();
    // inclusive Hillis-Steele scan of thread totals
    for (int d = 1; d < 256; d <<= 1) {
        int v = (tid >= d) ? sm[tid - d] : 0;
        __syncthreads();
        sm[tid] += v;
        __syncthreads();
    }
    const int texcl = sm[tid] - run;
    // publish block total, then grid barrier (all 74 blocks are resident => safe spin)
    if (tid == 255) {
        g_blk[bid] = sm[255];
        __threadfence();
        atomicAdd(&g_bar, 1);
        while (atomicAdd(&g_bar, 0) < NBLK) { }
        __threadfence();
    }
    __syncthreads();
    // block offset = sum of previous block totals
    int v2 = (tid < bid) ? g_blk[tid] : 0;     // bid <= 73 < 256
    sm[tid] = v2;
    __syncthreads();
    for (int d = 128; d >= 1; d >>= 1) {
        if (tid < d) sm[tid] += sm[tid + d];
        __syncthreads();
    }
    const int offset = sm[0];
#pragma unroll
    for (int t = 0; t < 16; t++) {
        if (base + t < TN) {
            int val = offset + texcl + c[t];
            g_rowptr[base + t] = val;
            g_cur[base + t] = val;
        }
    }
}

// ---- fill CSR: 4 edges per thread; also resets the scan barrier ----
__global__ void fill_kernel(const int* __restrict__ edges) {
    int e4 = blockIdx.x * blockDim.x + threadIdx.x;
    if (e4 == 0) g_bar = 0;     // stream-ordered after scan kernel => race-free reset
    if (e4 >= EE / 4) return;
    const uint4* ep = (const uint4*)(edges + 12 * e4);
    uint4 v0 = __ldcs(ep + 0);   // s0 r0 d0 s1
    uint4 v1 = __ldcs(ep + 1);   // r1 d1 s2 r2
    uint4 v2 = __ldcs(ep + 2);   // d2 s3 r3 d3
    int s0 = (int)v0.x, r0 = (int)v0.y, d0 = (int)v0.z;
    int s1 = (int)v0.w, r1 = (int)v1.x, d1 = (int)v1.y;
    int s2 = (int)v1.z, r2 = (int)v1.w, d2 = (int)v2.x;
    int s3 = (int)v2.y, r3 = (int)v2.z, d3 = (int)v2.w;
    int p0 = atomicAdd(&g_cur[((r0 >= RR) + (r0 >= 2 * RR)) * NN + d0], 1);
    int p1 = atomicAdd(&g_cur[((r1 >= RR) + (r1 >= 2 * RR)) * NN + d1], 1);
    int p2 = atomicAdd(&g_cur[((r2 >= RR) + (r2 >= 2 * RR)) * NN + d2], 1);
    int p3 = atomicAdd(&g_cur[((r3 >= RR) + (r3 >= 2 * RR)) * NN + d3], 1);
    g_eidx[p0] = s0;
    g_eidx[p1] = s1;
    g_eidx[p2] = s2;
    g_eidx[p3] = s3;
}

// ---- gather: warp per segment; fp32 rows (float4/lane, no cvt in the loop),
//      fp32 accumulate, half2 pack once per segment, streaming store ----
__global__ void gather_kernel(const float* __restrict__ Xf, int layer) {
    int gw = (blockIdx.x * blockDim.x + threadIdx.x) >> 5;
    int lane = threadIdx.x & 31;
    if (gw >= TN) return;
    const float* X = layer ? g_x1f : Xf;
    int s = __ldg(&g_rowptr[gw]);
    int e = (gw + 1 < TN) ? __ldg(&g_rowptr[gw + 1]) : EE;
    float a0 = 0.f, a1 = 0.f, a2 = 0.f, a3 = 0.f;
    float b0 = 0.f, b1 = 0.f, b2 = 0.f, b3 = 0.f;
    int j = s;
    for (; j + 2 <= e; j += 2) {
        int s0 = __ldcs(&g_eidx[j]);
        int s1 = __ldcs(&g_eidx[j + 1]);
        float4 w0 = __ldg((const float4*)(X + (size_t)s0 * DD) + lane);
        float4 w1 = __ldg((const float4*)(X + (size_t)s1 * DD) + lane);
        a0 += w0.x; a1 += w0.y; a2 += w0.z; a3 += w0.w;
        b0 += w1.x; b1 += w1.y; b2 += w1.z; b3 += w1.w;
    }
    if (j < e) {
        int s0 = __ldcs(&g_eidx[j]);
        float4 w0 = __ldg((const float4*)(X + (size_t)s0 * DD) + lane);
        a0 += w0.x; a1 += w0.y; a2 += w0.z; a3 += w0.w;
    }
    uint2 st;
    st.x = pack_h2(a0 + b0, a1 + b1);
    st.y = pack_h2(a2 + b2, a3 + b3);
    __stcs((uint2*)(g_aggu + (size_t)gw * D2) + lane, st);   // evict-first: keep X hot in L2
}

// ---- fused transform on fp16 tensor cores (mma m16n8k16, fp32 accum):
//      relation GEMM (K=384) -> relu((.+cnt*b)/deg) -> self GEMM (K=128)
//      -> +bs -> LayerNorm.  CTA: 256 threads, 128 nodes x 128 outs.
//      layer==0 epilogue: write x1 in BOTH fp16 (own phase-2) and fp32 (gather).
//      layer==1 tail: zero this block's own 384 g_cnt entries for the next call. ----
__global__ __launch_bounds__(256) void transform_kernel(
    float* __restrict__ Out,
    const float* __restrict__ b3,    // (3,128)
    const float* __restrict__ bs,    // (128)
    const float* __restrict__ gamma, // (128)
    const float* __restrict__ beta,  // (128)
    int layer) {
    __shared__ unsigned As2[16 * ASTR2];               // [k2][node] half2-packed
    __shared__ __align__(16) unsigned Bs2[16 * BSTR2]; // [k2][out]
    __shared__ float Sred[2][128][2];

    const unsigned* Xh  = layer ? g_x1u : g_xu;
    const unsigned* Wt  = g_Wtu[layer];
    const unsigned* Wst = g_Wstu[layer];

    const int tid = threadIdx.x;
    const int lane = tid & 31;
    const int wid = tid >> 5;
    const int warp_m = wid & 3;
    const int warp_n = wid >> 2;
    const int grp = lane >> 2;
    const int tid4 = lane & 3;
    const int nodeBase = blockIdx.x * 128;

    float acc[2][8][4];
#pragma unroll
    for (int mt = 0; mt < 2; mt++)
#pragma unroll
        for (int t = 0; t < 8; t++)
#pragma unroll
            for (int q = 0; q < 4; q++) acc[mt][t][q] = 0.f;

    // ================= phase 1: K = 384 over agg =================
    for (int c = 0; c < 12; c++) {
        int r = c >> 2;
        int d20 = (c & 3) * 16;                   // half2 offset within row
        const unsigned* Ap = g_aggu + (size_t)r * NN * D2;
        const unsigned* Bp = Wt + r * D2 * DD;
#pragma unroll
        for (int t = 0; t < 2; t++) {
            int idx = tid + t * 256;              // 0..511
            int nl = idx >> 2, c4 = idx & 3;
            int n = nodeBase + nl; if (n >= NN) n = NN - 1;
            uint4 v = __ldg((const uint4*)(Ap + (size_t)n * D2 + d20) + c4);
            int kk = c4 * 4;
            As2[(kk + 0) * ASTR2 + nl] = v.x;
            As2[(kk + 1) * ASTR2 + nl] = v.y;
            As2[(kk + 2) * ASTR2 + nl] = v.z;
            As2[(kk + 3) * ASTR2 + nl] = v.w;
        }
#pragma unroll
        for (int t = 0; t < 2; t++) {
            int idx = tid + t * 256;
            int k2 = idx >> 5, o4 = idx & 31;
            uint4 v = __ldg((const uint4*)(Bp + (d20 + k2) * DD) + o4);
            *(uint4*)&Bs2[k2 * BSTR2 + o4 * 4] = v;
        }
        __syncthreads();
#pragma unroll
        for (int ks = 0; ks < 2; ks++) {
            int k20 = ks * 8;
            unsigned a[2][4];
#pragma unroll
            for (int mt = 0; mt < 2; mt++) {
                int mrow = warp_m * 32 + mt * 16 + grp;
                a[mt][0] = As2[(k20 + tid4) * ASTR2 + mrow];
                a[mt][1] = As2[(k20 + tid4) * ASTR2 + mrow + 8];
                a[mt][2] = As2[(k20 + tid4 + 4) * ASTR2 + mrow];
                a[mt][3] = As2[(k20 + tid4 + 4) * ASTR2 + mrow + 8];
            }
#pragma unroll
            for (int t = 0; t < 8; t++) {
                int oc = warp_n * 64 + t * 8 + grp;
                unsigned b0 = Bs2[(k20 + tid4) * BSTR2 + oc];
                unsigned b1 = Bs2[(k20 + tid4 + 4) * BSTR2 + oc];
                mma_f16(acc[0][t], a[0], b0, b1);
                mma_f16(acc[1][t], a[1], b0, b1);
            }
        }
        __syncthreads();
    }

    // ---------- mid epilogue: +cnt*bias, /degree, relu ----------
#pragma unroll
    for (int mt = 0; mt < 2; mt++) {
#pragma unroll
        for (int rr = 0; rr < 2; rr++) {
            int n = nodeBase + warp_m * 32 + mt * 16 + grp + rr * 8;
            if (n >= NN) n = NN - 1;
            float c0 = (float)__ldg(&g_cnt[n]);
            float c1 = (float)__ldg(&g_cnt[NN + n]);
            float c2 = (float)__ldg(&g_cnt[2 * NN + n]);
            float inv = 1.0f / fmaxf(c0 + c1 + c2, 1.0f);
#pragma unroll
            for (int t = 0; t < 8; t++) {
#pragma unroll
                for (int q = 0; q < 2; q++) {
                    int col = warp_n * 64 + t * 8 + 2 * tid4 + q;
                    int ci = rr * 2 + q;
                    float v = acc[mt][t][ci] + c0 * __ldg(&b3[col])
                            + c1 * __ldg(&b3[DD + col]) + c2 * __ldg(&b3[2 * DD + col]);
                    acc[mt][t][ci] = fmaxf(v * inv, 0.0f);
                }
            }
        }
    }

    // ================= phase 2: K = 128 self loop =================
    for (int c = 0; c < 4; c++) {
        int d20 = c * 16;
#pragma unroll
        for (int t = 0; t < 2; t++) {
            int idx = tid + t * 256;
            int nl = idx >> 2, c4 = idx & 3;
            int n = nodeBase + nl; if (n >= NN) n = NN - 1;
            uint4 v = __ldg((const uint4*)(Xh + (size_t)n * D2 + d20) + c4);
            int kk = c4 * 4;
            As2[(kk + 0) * ASTR2 + nl] = v.x;
            As2[(kk + 1) * ASTR2 + nl] = v.y;
            As2[(kk + 2) * ASTR2 + nl] = v.z;
            As2[(kk + 3) * ASTR2 + nl] = v.w;
        }
#pragma unroll
        for (int t = 0; t < 2; t++) {
            int idx = tid + t * 256;
            int k2 = idx >> 5, o4 = idx & 31;
            uint4 v = __ldg((const uint4*)(Wst + (d20 + k2) * DD) + o4);
            *(uint4*)&Bs2[k2 * BSTR2 + o4 * 4] = v;
        }
        __syncthreads();
#pragma unroll
        for (int ks = 0; ks < 2; ks++) {
            int k20 = ks * 8;
            unsigned a[2][4];
#pragma unroll
            for (int mt = 0; mt < 2; mt++) {
                int mrow = warp_m * 32 + mt * 16 + grp;
                a[mt][0] = As2[(k20 + tid4) * ASTR2 + mrow];
                a[mt][1] = As2[(k20 + tid4) * ASTR2 + mrow + 8];
                a[mt][2] = As2[(k20 + tid4 + 4) * ASTR2 + mrow];
                a[mt][3] = As2[(k20 + tid4 + 4) * ASTR2 + mrow + 8];
            }
#pragma unroll
            for (int t = 0; t < 8; t++) {
                int oc = warp_n * 64 + t * 8 + grp;
                unsigned b0 = Bs2[(k20 + tid4) * BSTR2 + oc];
                unsigned b1 = Bs2[(k20 + tid4 + 4) * BSTR2 + oc];
                mma_f16(acc[0][t], a[0], b0, b1);
                mma_f16(acc[1][t], a[1], b0, b1);
            }
        }
        __syncthreads();
    }

    // ---------- final epilogue: +bs, LayerNorm over 128 outs ----------
    float ps[2][2], ps2[2][2];
#pragma unroll
    for (int mt = 0; mt < 2; mt++) {
#pragma unroll
        for (int rr = 0; rr < 2; rr++) {
            float s = 0.f, s2 = 0.f;
#pragma unroll
            for (int t = 0; t < 8; t++) {
#pragma unroll
                for (int q = 0; q < 2; q++) {
                    int col = warp_n * 64 + t * 8 + 2 * tid4 + q;
                    int ci = rr * 2 + q;
                    float v = acc[mt][t][ci] + __ldg(&bs[col]);
                    acc[mt][t][ci] = v;
                    s += v; s2 += v * v;
                }
            }
            s  += __shfl_xor_sync(0xffffffffu, s, 1);
            s2 += __shfl_xor_sync(0xffffffffu, s2, 1);
            s  += __shfl_xor_sync(0xffffffffu, s, 2);
            s2 += __shfl_xor_sync(0xffffffffu, s2, 2);
            ps[mt][rr] = s; ps2[mt][rr] = s2;
            if (tid4 == 0) {
                int ln = warp_m * 32 + mt * 16 + grp + rr * 8;
                Sred[warp_n][ln][0] = s;
                Sred[warp_n][ln][1] = s2;
            }
        }
    }
    __syncthreads();
#pragma unroll
    for (int mt = 0; mt < 2; mt++) {
#pragma unroll
        for (int rr = 0; rr < 2; rr++) {
            int ln = warp_m * 32 + mt * 16 + grp + rr * 8;
            float s  = ps[mt][rr]  + Sred[1 - warp_n][ln][0];
            float s2 = ps2[mt][rr] + Sred[1 - warp_n][ln][1];
            float mean = s * (1.0f / 128.0f);
            float var  = s2 * (1.0f / 128.0f) - mean * mean;
            float rstd = rsqrtf(var + LN_EPS);
            int n = nodeBase + ln;
            if (n < NN) {
#pragma unroll
                for (int t = 0; t < 8; t++) {
                    int col = warp_n * 64 + t * 8 + 2 * tid4;
                    float ox = (acc[mt][t][rr * 2 + 0] - mean) * rstd * __ldg(&gamma[col]) + __ldg(&beta[col]);
                    float oy = (acc[mt][t][rr * 2 + 1] - mean) * rstd * __ldg(&gamma[col + 1]) + __ldg(&beta[col + 1]);
                    if (layer == 0) {
                        g_x1u[(size_t)n * D2 + (col >> 1)] = pack_h2(ox, oy);
                        __stcs((float2*)(g_x1f + (size_t)n * DD + col), make_float2(ox, oy));
                    } else {
                        *(float2*)(Out + (size_t)n * DD + col) = make_float2(ox, oy);
                    }
                }
            }
        }
    }

    // ---------- layer-1 tail: zero this block's own g_cnt entries (128 nodes x 3 buckets).
    //            Only this block reads these entries (mid-epilogue above), so no race. ----
    if (layer == 1) {
#pragma unroll
        for (int i = tid; i < 384; i += 256) {
            int node = nodeBase + (i & 127);
            int region = i >> 7;
            if (node < NN) g_cnt[region * NN + node] = 0;
        }
    }
}

extern "C" void kernel_launch(void* const* d_in, const int* in_sizes, int n_in,
                              void* d_out, int out_size) {
    const int*   edges    = (const int*)d_in[0];
    const float* node_emb = (const float*)d_in[1];
    const float* W1  = (const float*)d_in[2];
    const float* b1  = (const float*)d_in[3];
    const float* Ws1 = (const float*)d_in[4];
    const float* bs1 = (const float*)d_in[5];
    const float* g1  = (const float*)d_in[6];
    const float* be1 = (const float*)d_in[7];
    const float* W2  = (const float*)d_in[8];
    const float* b2  = (const float*)d_in[9];
    const float* Ws2 = (const float*)d_in[10];
    const float* bs2 = (const float*)d_in[11];
    const float* g2  = (const float*)d_in[12];
    const float* be2 = (const float*)d_in[13];
    float* out = (float*)d_out;

    prep_kernel<<<PREP_BLKS, 256>>>(W1, Ws1, W2, Ws2, node_emb, edges);
    scan_fused_kernel<<<NBLK, 256>>>();
    fill_kernel<<<(EE / 4 + 255) / 256, 256>>>(edges);
    gather_kernel<<<(TN * 32 + 255) / 256, 256>>>(node_emb, 0);
    transform_kernel<<<(NN + 127) / 128, 256>>>(out, b1, bs1, g1, be1, 0);
    gather_kernel<<<(TN * 32 + 255) / 256, 256>>>(node_emb, 1);
    transform_kernel<<<(NN + 127) / 128, 256>>>(out, b2, bs2, g2, be2, 1);
}

// round 17
// speedup vs baseline: 1.2299x; 1.2299x over previous
#include <cuda_runtime.h>
#include <cuda_fp16.h>

#define NN 100000
#define EE 1600000
#define TN (3 * NN)
#define DD 128
#define D2 64             // half2 per row
#define RR 400
#define LN_EPS 1e-5f
#define ASTR2 137         // As smem stride in half2 words
#define BSTR2 136         // Bs smem stride in half2 words (mult of 4; conflict-free mma loads)
#define SCAN_BLK 4096
#define NBLK ((TN + SCAN_BLK - 1) / SCAN_BLK)   // 74  (< 148 SMs => whole grid resident)

// prep kernel block ranges (pack weights + convert x + per-bucket degree count, 4 edges/thread)
#define PREP_PACK_BLKS 256        // 8 * 8192 half2 / 256
#define PREP_XCV_BLKS 12500       // NN*D2/2 uint2 / 256
#define PREP_CNT_BLKS 1563        // ceil(EE/4/256)
#define PREP_BLKS (PREP_PACK_BLKS + PREP_XCV_BLKS + PREP_CNT_BLKS)

// ---- scratch (static device globals; no allocations allowed) ----
__device__ __align__(16) unsigned g_aggu[(size_t)TN * D2];  // aggregated features, half2
__device__ __align__(16) unsigned g_xu[(size_t)NN * D2];    // node_emb as half2
__device__ __align__(16) unsigned g_x1u[(size_t)NN * D2];   // layer-1 output as half2
__device__ int      g_cnt[TN];                  // statically zero; re-zeroed in transform(1) tail
__device__ int      g_rowptr[TN];
__device__ int      g_cur[TN];
__device__ int      g_blk[128];
__device__ int      g_bar;                      // scan grid barrier; reset by fill_kernel
__device__ int      g_eidx[EE];
__device__ unsigned g_Wtu[2][3 * D2 * DD];      // relation weights, k-pair-major half2: [d2][o]
__device__ unsigned g_Wstu[2][D2 * DD];         // self weights, same layout

__device__ __forceinline__ unsigned pack_h2(float a, float b) {
    __half2 h = __floats2half2_rn(a, b);
    return *reinterpret_cast<unsigned*>(&h);
}
__device__ __forceinline__ float2 unpack_h2(unsigned u) {
    return __half22float2(*reinterpret_cast<__half2*>(&u));
}

__device__ __forceinline__ void mma_f16(float* c, const unsigned* a, unsigned b0, unsigned b1) {
    asm volatile(
        "mma.sync.aligned.m16n8k16.row.col.f32.f16.f16.f32 "
        "{%0,%1,%2,%3},{%4,%5,%6,%7},{%8,%9},{%0,%1,%2,%3};\n"
        : "+f"(c[0]), "+f"(c[1]), "+f"(c[2]), "+f"(c[3])
        : "r"(a[0]), "r"(a[1]), "r"(a[2]), "r"(a[3]), "r"(b0), "r"(b1));
}

// ---- fused prep: pack weights; convert x to half2; degree count (4 edges/thread) ----
__global__ void prep_kernel(const float* __restrict__ W1, const float* __restrict__ Ws1,
                            const float* __restrict__ W2, const float* __restrict__ Ws2,
                            const float* __restrict__ x, const int* __restrict__ edges) {
    int b = blockIdx.x;
    int tid = threadIdx.x;
    if (b < PREP_PACK_BLKS) {
        int idx = b * 256 + tid;                 // 8 matrices * 8192 half2
        int m = idx >> 13;
        int e = idx & (D2 * DD - 1);
        int d2 = e >> 7;                         // k-pair index 0..63
        int o = e & 127;
        const float* src;
        unsigned* dst;
        if (m < 3)       { src = W1 + m * DD * DD;       dst = g_Wtu[0] + m * D2 * DD; }
        else if (m == 3) { src = Ws1;                    dst = g_Wstu[0]; }
        else if (m < 7)  { src = W2 + (m - 4) * DD * DD; dst = g_Wtu[1] + (m - 4) * D2 * DD; }
        else             { src = Ws2;                    dst = g_Wstu[1]; }
        dst[d2 * DD + o] = pack_h2(src[o * DD + 2 * d2], src[o * DD + 2 * d2 + 1]);
    } else if (b < PREP_PACK_BLKS + PREP_XCV_BLKS) {
        int i = (b - PREP_PACK_BLKS) * 256 + tid;   // NN*D2/2 uint2 stores
        float4 v = __ldg((const float4*)x + i);
        uint2 o;
        o.x = pack_h2(v.x, v.y);
        o.y = pack_h2(v.z, v.w);
        ((uint2*)g_xu)[i] = o;
    } else {
        // degree count: 4 edges per thread via 3 aligned uint4 loads (MLP=4 atomics)
        int e4 = (b - PREP_PACK_BLKS - PREP_XCV_BLKS) * 256 + tid;
        if (e4 < EE / 4) {
            const uint4* ep = (const uint4*)(edges + 12 * e4);
            uint4 v0 = __ldcs(ep + 0);   // s0 r0 d0 s1
            uint4 v1 = __ldcs(ep + 1);   // r1 d1 s2 r2
            uint4 v2 = __ldcs(ep + 2);   // d2 s3 r3 d3
            int r0 = (int)v0.y, d0 = (int)v0.z;
            int r1 = (int)v1.x, d1 = (int)v1.y;
            int r2 = (int)v1.w, d2 = (int)v2.x;
            int r3 = (int)v2.z, d3 = (int)v2.w;
            atomicAdd(&g_cnt[((r0 >= RR) + (r0 >= 2 * RR)) * NN + d0], 1);
            atomicAdd(&g_cnt[((r1 >= RR) + (r1 >= 2 * RR)) * NN + d1], 1);
            atomicAdd(&g_cnt[((r2 >= RR) + (r2 >= 2 * RR)) * NN + d2], 1);
            atomicAdd(&g_cnt[((r3 >= RR) + (r3 >= 2 * RR)) * NN + d3], 1);
        }
    }
}

// ---- fused exclusive scan (single kernel, resident-grid spin barrier) ----
__global__ __launch_bounds__(256) void scan_fused_kernel() {
    __shared__ int sm[256];
    const int tid = threadIdx.x;
    const int bid = blockIdx.x;
    const int base = bid * SCAN_BLK + tid * 16;
    int c[16];
    int run = 0;
#pragma unroll
    for (int t = 0; t < 16; t++) {
        int v = (base + t < TN) ? g_cnt[base + t] : 0;
        c[t] = run;
        run += v;
    }
    sm[tid] = run;
    __syncthreads();
    // inclusive Hillis-Steele scan of thread totals
    for (int d = 1; d < 256; d <<= 1) {
        int v = (tid >= d) ? sm[tid - d] : 0;
        __syncthreads();
        sm[tid] += v;
        __syncthreads();
    }
    const int texcl = sm[tid] - run;
    // publish block total, then grid barrier (all 74 blocks are resident => safe spin)
    if (tid == 255) {
        g_blk[bid] = sm[255];
        __threadfence();
        atomicAdd(&g_bar, 1);
        while (atomicAdd(&g_bar, 0) < NBLK) { }
        __threadfence();
    }
    __syncthreads();
    // block offset = sum of previous block totals
    int v2 = (tid < bid) ? g_blk[tid] : 0;     // bid <= 73 < 256
    sm[tid] = v2;
    __syncthreads();
    for (int d = 128; d >= 1; d >>= 1) {
        if (tid < d) sm[tid] += sm[tid + d];
        __syncthreads();
    }
    const int offset = sm[0];
#pragma unroll
    for (int t = 0; t < 16; t++) {
        if (base + t < TN) {
            int val = offset + texcl + c[t];
            g_rowptr[base + t] = val;
            g_cur[base + t] = val;
        }
    }
}

// ---- fill CSR: 4 edges per thread; also resets the scan barrier ----
__global__ void fill_kernel(const int* __restrict__ edges) {
    int e4 = blockIdx.x * blockDim.x + threadIdx.x;
    if (e4 == 0) g_bar = 0;     // stream-ordered after scan kernel => race-free reset
    if (e4 >= EE / 4) return;
    const uint4* ep = (const uint4*)(edges + 12 * e4);
    uint4 v0 = __ldcs(ep + 0);   // s0 r0 d0 s1
    uint4 v1 = __ldcs(ep + 1);   // r1 d1 s2 r2
    uint4 v2 = __ldcs(ep + 2);   // d2 s3 r3 d3
    int s0 = (int)v0.x, r0 = (int)v0.y, d0 = (int)v0.z;
    int s1 = (int)v0.w, r1 = (int)v1.x, d1 = (int)v1.y;
    int s2 = (int)v1.z, r2 = (int)v1.w, d2 = (int)v2.x;
    int s3 = (int)v2.y, r3 = (int)v2.z, d3 = (int)v2.w;
    int p0 = atomicAdd(&g_cur[((r0 >= RR) + (r0 >= 2 * RR)) * NN + d0], 1);
    int p1 = atomicAdd(&g_cur[((r1 >= RR) + (r1 >= 2 * RR)) * NN + d1], 1);
    int p2 = atomicAdd(&g_cur[((r2 >= RR) + (r2 >= 2 * RR)) * NN + d2], 1);
    int p3 = atomicAdd(&g_cur[((r3 >= RR) + (r3 >= 2 * RR)) * NN + d3], 1);
    g_eidx[p0] = s0;
    g_eidx[p1] = s1;
    g_eidx[p2] = s2;
    g_eidx[p3] = s3;
}

// ---- gather: warp per segment; half2 rows, HALF2 accumulation (HADD2, no cvt/pack),
//      streaming half2 store.  Bytes identical to the 350us baseline; ~half the instr. ----
__global__ void gather_kernel(int layer) {
    int gw = (blockIdx.x * blockDim.x + threadIdx.x) >> 5;
    int lane = threadIdx.x & 31;
    if (gw >= TN) return;
    const unsigned* X = layer ? g_x1u : g_xu;
    int s = __ldg(&g_rowptr[gw]);
    int e = (gw + 1 < TN) ? __ldg(&g_rowptr[gw + 1]) : EE;
    __half2 z = __floats2half2_rn(0.f, 0.f);
    __half2 a0 = z, a1 = z, b0 = z, b1 = z;
    int j = s;
    for (; j + 2 <= e; j += 2) {
        int s0 = __ldcs(&g_eidx[j]);
        int s1 = __ldcs(&g_eidx[j + 1]);
        uint2 w0 = __ldg((const uint2*)(X + (size_t)s0 * D2) + lane);
        uint2 w1 = __ldg((const uint2*)(X + (size_t)s1 * D2) + lane);
        a0 = __hadd2(a0, *reinterpret_cast<__half2*>(&w0.x));
        a1 = __hadd2(a1, *reinterpret_cast<__half2*>(&w0.y));
        b0 = __hadd2(b0, *reinterpret_cast<__half2*>(&w1.x));
        b1 = __hadd2(b1, *reinterpret_cast<__half2*>(&w1.y));
    }
    if (j < e) {
        int s0 = __ldcs(&g_eidx[j]);
        uint2 w0 = __ldg((const uint2*)(X + (size_t)s0 * D2) + lane);
        a0 = __hadd2(a0, *reinterpret_cast<__half2*>(&w0.x));
        a1 = __hadd2(a1, *reinterpret_cast<__half2*>(&w0.y));
    }
    __half2 r0 = __hadd2(a0, b0);
    __half2 r1 = __hadd2(a1, b1);
    uint2 st;
    st.x = *reinterpret_cast<unsigned*>(&r0);
    st.y = *reinterpret_cast<unsigned*>(&r1);
    __stcs((uint2*)(g_aggu + (size_t)gw * D2) + lane, st);   // evict-first: keep X hot in L2
}

// ---- fused transform on fp16 tensor cores (mma m16n8k16, fp32 accum):
//      relation GEMM (K=384) -> relu((.+cnt*b)/deg) -> self GEMM (K=128)
//      -> +bs -> LayerNorm.  CTA: 256 threads, 128 nodes x 128 outs.
//      layer==1 tail: zero this block's own 384 g_cnt entries for the next call. ----
__global__ __launch_bounds__(256) void transform_kernel(
    float* __restrict__ Out,
    const float* __restrict__ b3,    // (3,128)
    const float* __restrict__ bs,    // (128)
    const float* __restrict__ gamma, // (128)
    const float* __restrict__ beta,  // (128)
    int layer) {
    __shared__ unsigned As2[16 * ASTR2];               // [k2][node] half2-packed
    __shared__ __align__(16) unsigned Bs2[16 * BSTR2]; // [k2][out]
    __shared__ float Sred[2][128][2];

    const unsigned* Xh  = layer ? g_x1u : g_xu;
    const unsigned* Wt  = g_Wtu[layer];
    const unsigned* Wst = g_Wstu[layer];

    const int tid = threadIdx.x;
    const int lane = tid & 31;
    const int wid = tid >> 5;
    const int warp_m = wid & 3;
    const int warp_n = wid >> 2;
    const int grp = lane >> 2;
    const int tid4 = lane & 3;
    const int nodeBase = blockIdx.x * 128;

    float acc[2][8][4];
#pragma unroll
    for (int mt = 0; mt < 2; mt++)
#pragma unroll
        for (int t = 0; t < 8; t++)
#pragma unroll
            for (int q = 0; q < 4; q++) acc[mt][t][q] = 0.f;

    // ================= phase 1: K = 384 over agg =================
    for (int c = 0; c < 12; c++) {
        int r = c >> 2;
        int d20 = (c & 3) * 16;                   // half2 offset within row
        const unsigned* Ap = g_aggu + (size_t)r * NN * D2;
        const unsigned* Bp = Wt + r * D2 * DD;
#pragma unroll
        for (int t = 0; t < 2; t++) {
            int idx = tid + t * 256;              // 0..511
            int nl = idx >> 2, c4 = idx & 3;
            int n = nodeBase + nl; if (n >= NN) n = NN - 1;
            uint4 v = __ldg((const uint4*)(Ap + (size_t)n * D2 + d20) + c4);
            int kk = c4 * 4;
            As2[(kk + 0) * ASTR2 + nl] = v.x;
            As2[(kk + 1) * ASTR2 + nl] = v.y;
            As2[(kk + 2) * ASTR2 + nl] = v.z;
            As2[(kk + 3) * ASTR2 + nl] = v.w;
        }
#pragma unroll
        for (int t = 0; t < 2; t++) {
            int idx = tid + t * 256;
            int k2 = idx >> 5, o4 = idx & 31;
            uint4 v = __ldg((const uint4*)(Bp + (d20 + k2) * DD) + o4);
            *(uint4*)&Bs2[k2 * BSTR2 + o4 * 4] = v;
        }
        __syncthreads();
#pragma unroll
        for (int ks = 0; ks < 2; ks++) {
            int k20 = ks * 8;
            unsigned a[2][4];
#pragma unroll
            for (int mt = 0; mt < 2; mt++) {
                int mrow = warp_m * 32 + mt * 16 + grp;
                a[mt][0] = As2[(k20 + tid4) * ASTR2 + mrow];
                a[mt][1] = As2[(k20 + tid4) * ASTR2 + mrow + 8];
                a[mt][2] = As2[(k20 + tid4 + 4) * ASTR2 + mrow];
                a[mt][3] = As2[(k20 + tid4 + 4) * ASTR2 + mrow + 8];
            }
#pragma unroll
            for (int t = 0; t < 8; t++) {
                int oc = warp_n * 64 + t * 8 + grp;
                unsigned b0 = Bs2[(k20 + tid4) * BSTR2 + oc];
                unsigned b1 = Bs2[(k20 + tid4 + 4) * BSTR2 + oc];
                mma_f16(acc[0][t], a[0], b0, b1);
                mma_f16(acc[1][t], a[1], b0, b1);
            }
        }
        __syncthreads();
    }

    // ---------- mid epilogue: +cnt*bias, /degree, relu ----------
#pragma unroll
    for (int mt = 0; mt < 2; mt++) {
#pragma unroll
        for (int rr = 0; rr < 2; rr++) {
            int n = nodeBase + warp_m * 32 + mt * 16 + grp + rr * 8;
            if (n >= NN) n = NN - 1;
            float c0 = (float)__ldg(&g_cnt[n]);
            float c1 = (float)__ldg(&g_cnt[NN + n]);
            float c2 = (float)__ldg(&g_cnt[2 * NN + n]);
            float inv = 1.0f / fmaxf(c0 + c1 + c2, 1.0f);
#pragma unroll
            for (int t = 0; t < 8; t++) {
#pragma unroll
                for (int q = 0; q < 2; q++) {
                    int col = warp_n * 64 + t * 8 + 2 * tid4 + q;
                    int ci = rr * 2 + q;
                    float v = acc[mt][t][ci] + c0 * __ldg(&b3[col])
                            + c1 * __ldg(&b3[DD + col]) + c2 * __ldg(&b3[2 * DD + col]);
                    acc[mt][t][ci] = fmaxf(v * inv, 0.0f);
                }
            }
        }
    }

    // ================= phase 2: K = 128 self loop =================
    for (int c = 0; c < 4; c++) {
        int d20 = c * 16;
#pragma unroll
        for (int t = 0; t < 2; t++) {
            int idx = tid + t * 256;
            int nl = idx >> 2, c4 = idx & 3;
            int n = nodeBase + nl; if (n >= NN) n = NN - 1;
            uint4 v = __ldg((const uint4*)(Xh + (size_t)n * D2 + d20) + c4);
            int kk = c4 * 4;
            As2[(kk + 0) * ASTR2 + nl] = v.x;
            As2[(kk + 1) * ASTR2 + nl] = v.y;
            As2[(kk + 2) * ASTR2 + nl] = v.z;
            As2[(kk + 3) * ASTR2 + nl] = v.w;
        }
#pragma unroll
        for (int t = 0; t < 2; t++) {
            int idx = tid + t * 256;
            int k2 = idx >> 5, o4 = idx & 31;
            uint4 v = __ldg((const uint4*)(Wst + (d20 + k2) * DD) + o4);
            *(uint4*)&Bs2[k2 * BSTR2 + o4 * 4] = v;
        }
        __syncthreads();
#pragma unroll
        for (int ks = 0; ks < 2; ks++) {
            int k20 = ks * 8;
            unsigned a[2][4];
#pragma unroll
            for (int mt = 0; mt < 2; mt++) {
                int mrow = warp_m * 32 + mt * 16 + grp;
                a[mt][0] = As2[(k20 + tid4) * ASTR2 + mrow];
                a[mt][1] = As2[(k20 + tid4) * ASTR2 + mrow + 8];
                a[mt][2] = As2[(k20 + tid4 + 4) * ASTR2 + mrow];
                a[mt][3] = As2[(k20 + tid4 + 4) * ASTR2 + mrow + 8];
            }
#pragma unroll
            for (int t = 0; t < 8; t++) {
                int oc = warp_n * 64 + t * 8 + grp;
                unsigned b0 = Bs2[(k20 + tid4) * BSTR2 + oc];
                unsigned b1 = Bs2[(k20 + tid4 + 4) * BSTR2 + oc];
                mma_f16(acc[0][t], a[0], b0, b1);
                mma_f16(acc[1][t], a[1], b0, b1);
            }
        }
        __syncthreads();
    }

    // ---------- final epilogue: +bs, LayerNorm over 128 outs ----------
    float ps[2][2], ps2[2][2];
#pragma unroll
    for (int mt = 0; mt < 2; mt++) {
#pragma unroll
        for (int rr = 0; rr < 2; rr++) {
            float s = 0.f, s2 = 0.f;
#pragma unroll
            for (int t = 0; t < 8; t++) {
#pragma unroll
                for (int q = 0; q < 2; q++) {
                    int col = warp_n * 64 + t * 8 + 2 * tid4 + q;
                    int ci = rr * 2 + q;
                    float v = acc[mt][t][ci] + __ldg(&bs[col]);
                    acc[mt][t][ci] = v;
                    s += v; s2 += v * v;
                }
            }
            s  += __shfl_xor_sync(0xffffffffu, s, 1);
            s2 += __shfl_xor_sync(0xffffffffu, s2, 1);
            s  += __shfl_xor_sync(0xffffffffu, s, 2);
            s2 += __shfl_xor_sync(0xffffffffu, s2, 2);
            ps[mt][rr] = s; ps2[mt][rr] = s2;
            if (tid4 == 0) {
                int ln = warp_m * 32 + mt * 16 + grp + rr * 8;
                Sred[warp_n][ln][0] = s;
                Sred[warp_n][ln][1] = s2;
            }
        }
    }
    __syncthreads();
#pragma unroll
    for (int mt = 0; mt < 2; mt++) {
#pragma unroll
        for (int rr = 0; rr < 2; rr++) {
            int ln = warp_m * 32 + mt * 16 + grp + rr * 8;
            float s  = ps[mt][rr]  + Sred[1 - warp_n][ln][0];
            float s2 = ps2[mt][rr] + Sred[1 - warp_n][ln][1];
            float mean = s * (1.0f / 128.0f);
            float var  = s2 * (1.0f / 128.0f) - mean * mean;
            float rstd = rsqrtf(var + LN_EPS);
            int n = nodeBase + ln;
            if (n < NN) {
#pragma unroll
                for (int t = 0; t < 8; t++) {
                    int col = warp_n * 64 + t * 8 + 2 * tid4;
                    float ox = (acc[mt][t][rr * 2 + 0] - mean) * rstd * __ldg(&gamma[col]) + __ldg(&beta[col]);
                    float oy = (acc[mt][t][rr * 2 + 1] - mean) * rstd * __ldg(&gamma[col + 1]) + __ldg(&beta[col + 1]);
                    if (layer == 0) {
                        g_x1u[(size_t)n * D2 + (col >> 1)] = pack_h2(ox, oy);
                    } else {
                        *(float2*)(Out + (size_t)n * DD + col) = make_float2(ox, oy);
                    }
                }
            }
        }
    }

    // ---------- layer-1 tail: zero this block's own g_cnt entries (128 nodes x 3 buckets).
    //            Only this block reads these entries (mid-epilogue above), so no race. ----
    if (layer == 1) {
#pragma unroll
        for (int i = tid; i < 384; i += 256) {
            int node = nodeBase + (i & 127);
            int region = i >> 7;
            if (node < NN) g_cnt[region * NN + node] = 0;
        }
    }
}

extern "C" void kernel_launch(void* const* d_in, const int* in_sizes, int n_in,
                              void* d_out, int out_size) {
    const int*   edges    = (const int*)d_in[0];
    const float* node_emb = (const float*)d_in[1];
    const float* W1  = (const float*)d_in[2];
    const float* b1  = (const float*)d_in[3];
    const float* Ws1 = (const float*)d_in[4];
    const float* bs1 = (const float*)d_in[5];
    const float* g1  = (const float*)d_in[6];
    const float* be1 = (const float*)d_in[7];
    const float* W2  = (const float*)d_in[8];
    const float* b2  = (const float*)d_in[9];
    const float* Ws2 = (const float*)d_in[10];
    const float* bs2 = (const float*)d_in[11];
    const float* g2  = (const float*)d_in[12];
    const float* be2 = (const float*)d_in[13];
    float* out = (float*)d_out;

    prep_kernel<<<PREP_BLKS, 256>>>(W1, Ws1, W2, Ws2, node_emb, edges);
    scan_fused_kernel<<<NBLK, 256>>>();
    fill_kernel<<<(EE / 4 + 255) / 256, 256>>>(edges);
    gather_kernel<<<(TN * 32 + 255) / 256, 256>>>(0);
    transform_kernel<<<(NN + 127) / 128, 256>>>(out, b1, bs1, g1, be1, 0);
    gather_kernel<<<(TN * 32 + 255) / 256, 256>>>(1);
    transform_kernel<<<(NN + 127) / 128, 256>>>(out, b2, bs2, g2, be2, 1);
}